// round 11
// baseline (speedup 1.0000x reference)
#include <cuda_runtime.h>
#include <math.h>

#define BB 4
#define DD 256
#define NN 2048
#define HH 4
#define HDIM 64
#define TS 64          // attention tile
#define TP 68          // padded row length

// ---------------- scratch (no allocations allowed) ----------------
__device__ float g_q[BB*DD*NN];
__device__ float g_k[BB*DD*NN];
__device__ float g_v[BB*DD*NN];
__device__ float g_msg[BB*DD*NN];
__device__ float g_h2[BB*2*DD*NN];
__device__ float g_wfull[2*DD*2*DD];   // [512][512]: [W1x | W1m@Wm]
__device__ float g_bc[2*DD];           // b1 + W1m@bm

// ---------------- GEMM body: 128x128 tile, 8x8 microtile, register prefetch ----------------
// C = relu?(A @ [B0; B1] + bias) for the (blockIdx.y, blockIdx.x) 128x128 tile.
// A: [M,K]-logical with row stride lda (mult of 4). B0 k-rows [0,Ksplit) stride ldb,
// B1 the rest. C row stride ldc. bias nullable. All tiles moved as float4.
__device__ __forceinline__
void gemm_body(const float* __restrict__ A,
               const float* __restrict__ B0, const float* __restrict__ B1,
               float* __restrict__ C, const float* __restrict__ bias,
               int K, int Ksplit, int lda, int ldb, int ldc, int relu)
{
    __shared__ float As[16][132];
    __shared__ float Bs[16][132];

    const int iBase = blockIdx.y * 128;
    const int jBase = blockIdx.x * 128;
    const int tid = threadIdx.x;
    const int i0 = (tid & 15) * 4;    // rows: i0..i0+3 and i0+64..i0+67
    const int j0 = (tid >> 4) * 4;    // cols: j0..j0+3 and j0+64..j0+67

    // per-thread fixed load coordinates (float4 granularity)
    const int aK4 = tid & 3,  aI = tid >> 2;   // A: k = 4*aK4.., i = aI + rep*64
    const int bJ4 = tid & 31, bK = tid >> 5;   // B: j = 4*bJ4.., k = bK + rep*8

    float acc[8][8];
#pragma unroll
    for (int r = 0; r < 8; r++)
#pragma unroll
        for (int c = 0; c < 8; c++) acc[r][c] = 0.f;

    float4 ra[2], rb[2];

    // ---- prologue: load tile kt=0 into registers (LDG.128)
    {
#pragma unroll
        for (int rep = 0; rep < 2; rep++)
            ra[rep] = *(const float4*)&A[(long long)(iBase + aI + rep * 64) * lda + 4 * aK4];
#pragma unroll
        for (int rep = 0; rep < 2; rep++) {
            int krow = bK + rep * 8;
            const float* src = (krow < Ksplit)
                ? (B0 + (long long)krow * ldb)
                : (B1 + (long long)(krow - Ksplit) * ldb);
            rb[rep] = *(const float4*)&src[jBase + 4 * bJ4];
        }
    }

    for (int kt = 0; kt < K; kt += 16) {
        // ---- commit staged tile to smem
#pragma unroll
        for (int rep = 0; rep < 2; rep++) {
            As[4 * aK4 + 0][aI + rep * 64] = ra[rep].x;
            As[4 * aK4 + 1][aI + rep * 64] = ra[rep].y;
            As[4 * aK4 + 2][aI + rep * 64] = ra[rep].z;
            As[4 * aK4 + 3][aI + rep * 64] = ra[rep].w;
        }
#pragma unroll
        for (int rep = 0; rep < 2; rep++)
            *(float4*)&Bs[bK + rep * 8][4 * bJ4] = rb[rep];
        __syncthreads();

        // ---- prefetch next tile into registers (LDG latency hidden by FFMA below)
        if (kt + 16 < K) {
            const int ktn = kt + 16;
#pragma unroll
            for (int rep = 0; rep < 2; rep++)
                ra[rep] = *(const float4*)&A[(long long)(iBase + aI + rep * 64) * lda + ktn + 4 * aK4];
#pragma unroll
            for (int rep = 0; rep < 2; rep++) {
                int krow = ktn + bK + rep * 8;
                const float* src = (krow < Ksplit)
                    ? (B0 + (long long)krow * ldb)
                    : (B1 + (long long)(krow - Ksplit) * ldb);
                rb[rep] = *(const float4*)&src[jBase + 4 * bJ4];
            }
        }

        // ---- compute
#pragma unroll
        for (int kk = 0; kk < 16; kk++) {
            float4 a0 = *(const float4*)&As[kk][i0];
            float4 a1 = *(const float4*)&As[kk][i0 + 64];
            float4 b0 = *(const float4*)&Bs[kk][j0];
            float4 b1 = *(const float4*)&Bs[kk][j0 + 64];
            const float arr[8] = {a0.x, a0.y, a0.z, a0.w, a1.x, a1.y, a1.z, a1.w};
            const float brr[8] = {b0.x, b0.y, b0.z, b0.w, b1.x, b1.y, b1.z, b1.w};
#pragma unroll
            for (int r = 0; r < 8; r++)
#pragma unroll
                for (int c = 0; c < 8; c++)
                    acc[r][c] += arr[r] * brr[c];
        }
        __syncthreads();
    }

    // epilogue: bias + optional relu, float4 stores
#pragma unroll
    for (int ih = 0; ih < 2; ih++) {
#pragma unroll
        for (int r = 0; r < 4; r++) {
            int gi = iBase + i0 + ih * 64 + r;
            float bv = bias ? bias[gi] : 0.f;
#pragma unroll
            for (int jh = 0; jh < 2; jh++) {
                int gj = jBase + j0 + jh * 64;
                float4 o;
                o.x = acc[ih * 4 + r][jh * 4 + 0] + bv;
                o.y = acc[ih * 4 + r][jh * 4 + 1] + bv;
                o.z = acc[ih * 4 + r][jh * 4 + 2] + bv;
                o.w = acc[ih * 4 + r][jh * 4 + 3] + bv;
                if (relu) {
                    o.x = fmaxf(o.x, 0.f); o.y = fmaxf(o.y, 0.f);
                    o.z = fmaxf(o.z, 0.f); o.w = fmaxf(o.w, 0.f);
                }
                *(float4*)&C[(long long)gi * ldc + gj] = o;
            }
        }
    }
}

// generic batched entry (batch in blockIdx.z), ld = NN for B and C
__global__ __launch_bounds__(256)
void gemm128_k(const float* __restrict__ A,
               const float* __restrict__ B0, const float* __restrict__ B1,
               float* __restrict__ C, const float* __restrict__ bias,
               int K, int Ksplit, int lda, int relu)
{
    const int M = gridDim.y * 128;
    const long long bz = blockIdx.z;
    gemm_body(A,
              B0 + bz * (long long)Ksplit * NN,
              B1 + bz * (long long)(K - Ksplit) * NN,
              C  + bz * (long long)M * NN,
              bias, K, Ksplit, lda, NN, NN, relu);
}

// fused Q/K/V projections: blockIdx.z = w*4 + batch, w in {0,1,2}
__global__ __launch_bounds__(256)
void qkv_k(const float* __restrict__ Wq, const float* __restrict__ Wk,
           const float* __restrict__ Wv,
           const float* __restrict__ bq, const float* __restrict__ bk,
           const float* __restrict__ bv,
           const float* __restrict__ x, const float* __restrict__ source,
           float* __restrict__ q, float* __restrict__ k, float* __restrict__ v)
{
    const int w  = blockIdx.z >> 2;
    const int bz = blockIdx.z & 3;
    const float* A    = (w == 0) ? Wq : (w == 1) ? Wk : Wv;
    const float* bias = (w == 0) ? bq : (w == 1) ? bk : bv;
    const float* B    = (w == 0) ? x : source;
    float*       C    = (w == 0) ? q : (w == 1) ? k : v;
    const long long off = (long long)bz * DD * NN;
    gemm_body(A, B + off, B + off, C + off, bias, DD, DD, DD, NN, NN, 0);
}

// weight-fold GEMM: Wfull[:,256:512] = W1[:,256:512] @ Wm   (M=512, N=256, K=256)
// grid (256/128, 512/128) = (2, 4)
__global__ __launch_bounds__(256)
void fold_ww_k(const float* __restrict__ W1, const float* __restrict__ Wm,
               float* __restrict__ Wfull)
{
    gemm_body(W1 + DD, Wm, Wm, Wfull + DD, nullptr,
              DD, DD, 2 * DD, DD, 2 * DD, 0);
}

// copy left half: Wfull[:,0:256] = W1[:,0:256]
__global__ __launch_bounds__(256)
void fold_copy_k(const float* __restrict__ W1, float* __restrict__ Wfull)
{
    int idx = blockIdx.x * 256 + threadIdx.x;     // < 512*256
    int i = idx >> 8, k = idx & (DD - 1);
    Wfull[(long long)i * 2 * DD + k] = W1[(long long)i * 2 * DD + k];
}

// folded bias: bc = b1 + W1[:,256:512] @ bm   (512 threads)
__global__ __launch_bounds__(256)
void fold_bias_k(const float* __restrict__ W1, const float* __restrict__ bm,
                 const float* __restrict__ b1, float* __restrict__ bc)
{
    int i = blockIdx.x * 256 + threadIdx.x;       // < 512
    float s = b1[i];
    for (int k = 0; k < DD; k++)
        s += W1[(long long)i * 2 * DD + DD + k] * bm[k];
    bc[i] = s;
}

// ---------------- fused flash attention with edge weighting ----------------
// msg[b,d,h,n] = (sum_m exp(S-M)*edge[b,n,m]*v[b,d,h,m]) / (sum_m exp(S-M))
// S[n,m] = 0.125 * sum_d q[b,d,h,n]*k[b,d,h,m]
// Strided row ownership (rows ti+16a) for low-conflict PV reads; edge LDG.128s
// issued early (latency covered by the S FFMA block); all tile transfers float4.
__global__ __launch_bounds__(256, 3)
void flash_edge_k(const float* __restrict__ q, const float* __restrict__ k,
                  const float* __restrict__ v, const float* __restrict__ edge,
                  float* __restrict__ msg)
{
    extern __shared__ float smem[];
    float* Qs = smem;                  // [TS][TP]  Q tile [d][r]; reused as out staging
    float* Ks = Qs + TS * TP;          // [TS][TP]  K tile [d][m]; reused as edge tile [r][m]
    float* Vs = Ks + TS * TP;          // [TS][TP]  V tile [d][m]
    float* Ss = Vs + TS * TP;          // [TS][TP]  scores [r][m] -> P in place
    float* Mrow = Ss + TS * TP;        // [TS]
    float* Drow = Mrow + TS;           // [TS]
    float* Sc   = Drow + TS;           // [TS]

    const int z = blockIdx.y;
    const int b = z >> 2, h = z & 3;
    const int nBase = blockIdx.x * TS;
    const long long hd = (long long)HH * NN;
    const float* qp = q + (long long)b * DD * NN + (long long)h * NN;
    const float* kp = k + (long long)b * DD * NN + (long long)h * NN;
    const float* vp = v + (long long)b * DD * NN + (long long)h * NN;
    const float* ep = edge + (long long)b * NN * NN;

    const int tid = threadIdx.x;
    const int ti = tid & 15, tj = tid >> 4;
    const int c0 = tj * 4;                     // owned S cols / output dims
    // owned rows: ti + 16a, a = 0..3 (strided to break bank-conflict structure)
    const int t4 = tid & 15, tHi = tid >> 4;   // float4 transfer coords: col4 = t4, row = tHi + 16*rep

    // Q tile: Qs[d][r], float4 over r
#pragma unroll
    for (int rep = 0; rep < 4; rep++) {
        int d = tHi + rep * 16;
        *(float4*)&Qs[d * TP + 4 * t4] =
            *(const float4*)&qp[(long long)d * hd + nBase + 4 * t4];
    }
    if (tid < TS) { Mrow[tid] = -1e30f; Drow[tid] = 0.f; }

    float acc[4][4];
#pragma unroll
    for (int a = 0; a < 4; a++)
#pragma unroll
        for (int c = 0; c < 4; c++) acc[a][c] = 0.f;
    __syncthreads();

    for (int mBase = 0; mBase < NN; mBase += TS) {
        // K/V tiles [d][m], float4 over m
#pragma unroll
        for (int rep = 0; rep < 4; rep++) {
            int d = tHi + rep * 16;
            *(float4*)&Ks[d * TP + 4 * t4] =
                *(const float4*)&kp[(long long)d * hd + mBase + 4 * t4];
            *(float4*)&Vs[d * TP + 4 * t4] =
                *(const float4*)&vp[(long long)d * hd + mBase + 4 * t4];
        }
        __syncthreads();

        // ---- issue edge-tile LDG.128s early; latency hidden by the S FFMA block
        float4 er[4];
#pragma unroll
        for (int rep = 0; rep < 4; rep++)
            er[rep] = *(const float4*)&ep[(long long)(nBase + tHi + rep * 16) * NN + mBase + 4 * t4];

        // S[r][m], rows ti+16a: scalar Q reads (conflict-free), broadcast K reads
        float s[4][4];
#pragma unroll
        for (int a = 0; a < 4; a++)
#pragma unroll
            for (int c = 0; c < 4; c++) s[a][c] = 0.f;
#pragma unroll
        for (int dd = 0; dd < TS; dd++) {
            float qv[4];
#pragma unroll
            for (int a = 0; a < 4; a++) qv[a] = Qs[dd * TP + ti + 16 * a];
            float4 b4 = *(const float4*)&Ks[dd * TP + c0];
#pragma unroll
            for (int a = 0; a < 4; a++) {
                s[a][0] += qv[a] * b4.x; s[a][1] += qv[a] * b4.y;
                s[a][2] += qv[a] * b4.z; s[a][3] += qv[a] * b4.w;
            }
        }
        __syncthreads();   // done reading Ks (K data)

        // store S (rows ti+16a), and commit edge registers into Ks buffer: Es[r][m]
#pragma unroll
        for (int a = 0; a < 4; a++)
#pragma unroll
            for (int c = 0; c < 4; c++)
                Ss[(ti + 16 * a) * TP + c0 + c] = s[a][c] * 0.125f;
#pragma unroll
        for (int rep = 0; rep < 4; rep++)
            *(float4*)&Ks[(tHi + rep * 16) * TP + 4 * t4] = er[rep];
        __syncthreads();

        {
            const int row = tid >> 2, seg = tid & 3;
            float mx = -1e30f;
#pragma unroll
            for (int j = 0; j < 16; j++)
                mx = fmaxf(mx, Ss[row * TP + seg * 16 + j]);
            mx = fmaxf(mx, __shfl_xor_sync(0xffffffffu, mx, 1));
            mx = fmaxf(mx, __shfl_xor_sync(0xffffffffu, mx, 2));
            float Mold = Mrow[row];
            float Mnew = fmaxf(Mold, mx);
            float sum = 0.f;
#pragma unroll
            for (int j = 0; j < 16; j++) {
                int m = seg * 16 + j;
                float e = __expf(Ss[row * TP + m] - Mnew);
                sum += e;
                Ss[row * TP + m] = e * Ks[row * TP + m];   // P' = e * edge
            }
            sum += __shfl_xor_sync(0xffffffffu, sum, 1);
            sum += __shfl_xor_sync(0xffffffffu, sum, 2);
            if (seg == 0) {
                float scl = __expf(Mold - Mnew);
                Sc[row] = scl;
                Mrow[row] = Mnew;
                Drow[row] = Drow[row] * scl + sum;
            }
        }
        __syncthreads();

        {
            float scl[4];
#pragma unroll
            for (int a = 0; a < 4; a++) scl[a] = Sc[ti + 16 * a];
#pragma unroll
            for (int a = 0; a < 4; a++)
#pragma unroll
                for (int c = 0; c < 4; c++) acc[a][c] *= scl[a];
#pragma unroll 4
            for (int m = 0; m < TS; m += 4) {
                float4 p[4], vv[4];
#pragma unroll
                for (int a = 0; a < 4; a++) p[a]  = *(const float4*)&Ss[(ti + 16 * a) * TP + m];
#pragma unroll
                for (int c = 0; c < 4; c++) vv[c] = *(const float4*)&Vs[(c0 + c) * TP + m];
#pragma unroll
                for (int a = 0; a < 4; a++)
#pragma unroll
                    for (int c = 0; c < 4; c++)
                        acc[a][c] += p[a].x * vv[c].x + p[a].y * vv[c].y
                                   + p[a].z * vv[c].z + p[a].w * vv[c].w;
            }
        }
        __syncthreads();
    }

    // stage output (row = ti+16a, dim = c0+c) into Qs [d][r] for coalesced store
#pragma unroll
    for (int a = 0; a < 4; a++) {
        float inv = 1.f / Drow[ti + 16 * a];
#pragma unroll
        for (int c = 0; c < 4; c++)
            Qs[(c0 + c) * TP + ti + 16 * a] = acc[a][c] * inv;
    }
    __syncthreads();
    float* mp = msg + (long long)b * DD * NN + (long long)h * NN;
#pragma unroll
    for (int rep = 0; rep < 4; rep++) {
        int d = tHi + rep * 16;
        *(float4*)&mp[(long long)d * hd + nBase + 4 * t4] =
            *(const float4*)&Qs[d * TP + 4 * t4];
    }
}

// ---------------- host ----------------
extern "C" void kernel_launch(void* const* d_in, const int* in_sizes, int n_in,
                              void* d_out, int out_size)
{
    (void)in_sizes; (void)n_in; (void)out_size;
    const float* x      = (const float*)d_in[0];
    const float* source = (const float*)d_in[1];
    const float* edge   = (const float*)d_in[2];
    const float* Wq = (const float*)d_in[3];  const float* bq = (const float*)d_in[4];
    const float* Wk = (const float*)d_in[5];  const float* bk = (const float*)d_in[6];
    const float* Wv = (const float*)d_in[7];  const float* bv = (const float*)d_in[8];
    const float* Wm = (const float*)d_in[9];  const float* bm = (const float*)d_in[10];
    const float* W1 = (const float*)d_in[11]; const float* b1 = (const float*)d_in[12];
    const float* W2 = (const float*)d_in[13]; const float* b2 = (const float*)d_in[14];
    float* out = (float*)d_out;

    float *q, *k, *v, *msg, *h2, *wfull, *bc;
    cudaGetSymbolAddress((void**)&q,     g_q);
    cudaGetSymbolAddress((void**)&k,     g_k);
    cudaGetSymbolAddress((void**)&v,     g_v);
    cudaGetSymbolAddress((void**)&msg,   g_msg);
    cudaGetSymbolAddress((void**)&h2,    g_h2);
    cudaGetSymbolAddress((void**)&wfull, g_wfull);
    cudaGetSymbolAddress((void**)&bc,    g_bc);

    dim3 blk(256);

    // --- weight folding (tiny, off the fat dependency chain):
    // Wfull = [W1[:,0:256] | W1[:,256:512] @ Wm],  bc = b1 + W1[:,256:512] @ bm
    fold_copy_k<<<(2 * DD * DD) / 256, blk>>>(W1, wfull);
    fold_ww_k<<<dim3(DD / 128, (2 * DD) / 128), blk>>>(W1, Wm, wfull);
    fold_bias_k<<<(2 * DD) / 256, blk>>>(W1, bm, b1, bc);

    // --- fused projections: q/k/v in ONE launch (M=256, K=256, 384 CTAs)
    dim3 gqkv(NN / 128, DD / 128, 3 * BB);
    qkv_k<<<gqkv, blk>>>(Wq, Wk, Wv, bq, bk, bv, x, source, q, k, v);

    // --- fused attention (QK^T -> online softmax*edge -> PV), no prob tensor
    const int smemBytes = (4 * TS * TP + 3 * TS) * (int)sizeof(float);
    cudaFuncSetAttribute(flash_edge_k,
                         cudaFuncAttributeMaxDynamicSharedMemorySize, smemBytes);
    dim3 gfl(NN / TS, BB * HH);
    flash_edge_k<<<gfl, blk, smemBytes>>>(q, k, v, edge, msg);

    // --- h2 = relu(Wfull @ [x; msg] + bc)   (Wm GEMM folded away)
    dim3 gff1(NN / 128, (2 * DD) / 128, BB);
    gemm128_k<<<gff1, blk>>>(wfull, x, msg, h2, bc, 2 * DD, DD, 2 * DD, 1);

    // --- out = W2 @ h2 + b2       (M=256, K=512, single source)
    dim3 gff2(NN / 128, DD / 128, BB);
    gemm128_k<<<gff2, blk>>>(W2, h2, h2, out, b2, 2 * DD, 2 * DD, 2 * DD, 0);
}